// round 3
// baseline (speedup 1.0000x reference)
#include <cuda_runtime.h>
#include <stdint.h>

// ---------------- constants ----------------
#define MAXN_LAB (1 << 18)          // label scratch capacity (N = 200000 fits)
#define MAXC     128                // per-warp shared accumulator capacity
#define JW       4096               // columns per chunk (per warp)
#define ENC_NINF ((int)0x807FFFFF)  // order-preserving encoding of -inf

// ---------------- device scratch (static: no allocation) ----------------
__device__ unsigned char g_lab[MAXN_LAB + 8];
__device__ int g_is64;

// Order-preserving float<->int bijection (self-inverse):
//   f >= 0 : bits unchanged ; f < 0 : bits ^ 0x7fffffff
// Monotone: enc(a) > enc(b)  <=>  a > b  (for non-NaN).
__device__ __forceinline__ int enc_f(float f) {
    int i = __float_as_int(f);
    return (i >= 0) ? i : (i ^ 0x7fffffff);
}
__device__ __forceinline__ float dec_i(int i) {
    return __int_as_float((i >= 0) ? i : (i ^ 0x7fffffff));
}

// ---------------- kernel 0: init output + dtype flag ----------------
__global__ void smp_init(int* __restrict__ out_enc, int BC) {
    int i = blockIdx.x * blockDim.x + threadIdx.x;
    if (i < BC) out_enc[i] = ENC_NINF;        // encoded -inf (segment_max identity)
    if (i == 0) g_is64 = 1;                   // assume int64 until disproven
}

// ---------------- kernel 1: detect label width ----------------
// View the label buffer as int32[N] (safe for both widths). If labels are
// little-endian int64 with values in [0, C), every odd int32 word is 0.
// Any nonzero odd word => the buffer is really int32.
__global__ void smp_detect(const int* __restrict__ l32, int N) {
    int i = blockIdx.x * blockDim.x + threadIdx.x;
    if (i < N && (i & 1) && l32[i] != 0) g_is64 = 0;   // racy same-value store: fine
}

// ---------------- kernel 2: compact labels -> uint8 ----------------
__global__ void smp_compact(const void* __restrict__ labels, int N) {
    int i = blockIdx.x * blockDim.x + threadIdx.x;
    if (i < N) {
        int v = g_is64 ? (int)((const long long*)labels)[i]
                       : ((const int*)labels)[i];
        g_lab[i] = (unsigned char)v;
    }
}

// ---------------- kernel 3: main streaming max ----------------
// Grid: (ceil(N/JW), ceil(B/8)), 256 threads (8 warps). Warp w handles row
// blockIdx.y*8+w over columns [blockIdx.x*JW, +JW).
// Per-warp shared acc[] is a racy *threshold cache* (lower bound of the true
// max). Correctness comes solely from the global atomicMax on encoded ints;
// the cache merely filters ~99.99% of elements down to 1 LDS + compare.
__global__ __launch_bounds__(256) void smp_main(
    const float* __restrict__ vals, int* __restrict__ out_enc,
    int B, int N, int C)
{
    __shared__ float        accs[8][MAXC];
    __shared__ unsigned int labw[JW / 4];

    const int tid  = threadIdx.x;
    const int w    = tid >> 5;
    const int lane = tid & 31;
    const int j0   = blockIdx.x * JW;
    const int row  = blockIdx.y * 8 + w;
    const int n    = min(JW, N - j0);
    const int nw   = (n + 3) >> 2;

    // Stage this chunk's labels (uint8) into shared, 4 bytes at a time.
    for (int i = tid; i < nw; i += 256)
        labw[i] = ((const unsigned int*)g_lab)[(j0 >> 2) + i];

    const bool active = (row < B);
    int* orow = out_enc;  // set properly below if active
    if (active) {
        orow = out_enc + row * C;
        // Seed threshold cache from the current global result: later warps
        // inherit tight thresholds -> near-zero atomics.
        for (int c = lane; c < C; c += 32)
            accs[w][c] = dec_i(orow[c]);
    }
    __syncthreads();
    if (!active) return;

    float* acc = accs[w];

    if ((N & 3) == 0) {
        // Vectorized path: coalesced float4 stream (512B/warp/iter).
        const float4* rp = (const float4*)vals + (((size_t)row * N + j0) >> 2);
        const int n4 = n >> 2;
        #pragma unroll 4
        for (int i = lane; i < n4; i += 32) {
            float4 v = rp[i];
            unsigned int lw = labw[i];
            int c0 =  lw        & 0xff;
            int c1 = (lw >>  8) & 0xff;
            int c2 = (lw >> 16) & 0xff;
            int c3 =  lw >> 24;
            if (v.x > acc[c0]) { acc[c0] = v.x; atomicMax(orow + c0, enc_f(v.x)); }
            if (v.y > acc[c1]) { acc[c1] = v.y; atomicMax(orow + c1, enc_f(v.y)); }
            if (v.z > acc[c2]) { acc[c2] = v.z; atomicMax(orow + c2, enc_f(v.z)); }
            if (v.w > acc[c3]) { acc[c3] = v.w; atomicMax(orow + c3, enc_f(v.w)); }
        }
    } else {
        // Scalar fallback for N % 4 != 0 (not hit for this shape).
        const unsigned char* lb = (const unsigned char*)labw;
        const float* rp = vals + (size_t)row * N + j0;
        for (int i = lane; i < n; i += 32) {
            float v = rp[i];
            int c = lb[i];
            if (v > acc[c]) { acc[c] = v; atomicMax(orow + c, enc_f(v)); }
        }
    }
    // No final merge needed: the global atomics ARE the merge.
}

// ---------------- fallback: fully general (C > MAXC or N > MAXN_LAB) ----------------
__global__ void smp_naive(const float* __restrict__ vals, const void* __restrict__ labels,
                          int* __restrict__ out_enc, int B, int N, int C)
{
    long long total  = (long long)B * N;
    long long stride = (long long)gridDim.x * blockDim.x;
    int is64 = g_is64;
    for (long long idx = blockIdx.x * (long long)blockDim.x + threadIdx.x;
         idx < total; idx += stride) {
        int j = (int)(idx % N);
        int b = (int)(idx / N);
        int c = is64 ? (int)((const long long*)labels)[j]
                     : ((const int*)labels)[j];
        atomicMax(out_enc + b * C + c, enc_f(vals[idx]));
    }
}

// ---------------- kernel 4: decode in place ----------------
__global__ void smp_fin(int* __restrict__ io, int BC) {
    int i = blockIdx.x * blockDim.x + threadIdx.x;
    if (i < BC) {
        int e = io[i];
        io[i] = (e >= 0) ? e : (e ^ 0x7fffffff);  // bits of the float result
    }
}

// ---------------- launch ----------------
extern "C" void kernel_launch(void* const* d_in, const int* in_sizes, int n_in,
                              void* d_out, int out_size)
{
    const float* vals   = (const float*)d_in[0];
    const void*  labels = d_in[1];

    const int NV = in_sizes[0];      // B * N
    const int N  = in_sizes[1];      // 200000
    const int B  = NV / N;           // 128
    const int BC = out_size;         // B * C
    const int C  = BC / B;           // 100
    int* out_enc = (int*)d_out;

    const bool fast = (C <= MAXC) && (N <= MAXN_LAB) && ((size_t)B * N == (size_t)NV);

    int tmax = (N > BC) ? N : BC;
    smp_init  <<<(tmax + 255) / 256, 256>>>(out_enc, BC);
    smp_detect<<<(N + 255) / 256, 256>>>((const int*)labels, N);

    if (fast) {
        smp_compact<<<(N + 255) / 256, 256>>>(labels, N);
        dim3 grid((N + JW - 1) / JW, (B + 7) / 8);
        smp_main<<<grid, 256>>>(vals, out_enc, B, N, C);
    } else {
        smp_naive<<<1184, 256>>>(vals, labels, out_enc, B, N, C);
    }

    smp_fin<<<(BC + 255) / 256, 256>>>(out_enc, BC);
}